// round 2
// baseline (speedup 1.0000x reference)
#include <cuda_runtime.h>
#include <math.h>

// Problem constants
#define BQ 4
#define SQ 2048
#define DQ 1024
#define MROWS (BQ*SQ)          // 8192
#define NCH 8
#define CH (SQ/NCH)            // 256
#define NCTA 128
#define TPB 256

// ---------------- scratch (static __device__, no allocations) ----------------
__device__ float g_retained[MROWS*DQ];
__device__ float g_inp[MROWS*DQ];
__device__ float g_gate[MROWS*DQ];
__device__ float g_bm[MROWS*DQ];
__device__ float g_states[MROWS*DQ];
__device__ float g_E[NCH*BQ*DQ];
__device__ float g_Cr[NCH*BQ*DQ];
__device__ float g_blend[2][BQ*DQ];
__device__ unsigned g_arrive;
__device__ unsigned g_epoch;

__global__ void reset_bar() { g_arrive = 0u; g_epoch = 0u; }

// ---------------- retention scan (r = dec*r + k*v; retained = q*r) ----------
// pass1: per-chunk local end value E_c (starting from 0)
__global__ __launch_bounds__(TPB) void ret_pass1(const float* __restrict__ K_,
                                                 const float* __restrict__ V_,
                                                 const float* __restrict__ decay) {
    int gid = blockIdx.x * TPB + threadIdx.x;     // NCH*BQ*DQ threads
    int d = gid & (DQ - 1);
    int t2 = gid >> 10;
    int b = t2 & (BQ - 1);
    int c = t2 >> 2;
    float dec = decay[d >> 6];
    long base = ((long)(b * SQ + c * CH)) * DQ + d;
    float E = 0.f;
#pragma unroll 4
    for (int i = 0; i < CH; ++i) {
        E = fmaf(dec, E, K_[base] * V_[base]);
        base += DQ;
    }
    g_E[(c * BQ + b) * DQ + d] = E;
}

// pass2: exclusive scan of chunk carries
__global__ __launch_bounds__(TPB) void ret_pass2(const float* __restrict__ decay) {
    int gid = blockIdx.x * TPB + threadIdx.x;     // BQ*DQ threads
    int d = gid & (DQ - 1);
    int b = gid >> 10;
    float dec = decay[d >> 6];
    float p = dec;
#pragma unroll
    for (int i = 0; i < 8; ++i) p = p * p;        // dec^256
    float carry = 0.f;
    for (int c = 0; c < NCH; ++c) {
        int idx = (c * BQ + b) * DQ + d;
        g_Cr[idx] = carry;
        carry = fmaf(p, carry, g_E[idx]);
    }
}

// pass3: recompute chunk with carry-in, write retained = q*r
__global__ __launch_bounds__(TPB) void ret_pass3(const float* __restrict__ Q_,
                                                 const float* __restrict__ K_,
                                                 const float* __restrict__ V_,
                                                 const float* __restrict__ decay) {
    int gid = blockIdx.x * TPB + threadIdx.x;
    int d = gid & (DQ - 1);
    int t2 = gid >> 10;
    int b = t2 & (BQ - 1);
    int c = t2 >> 2;
    float dec = decay[d >> 6];
    float r = g_Cr[(c * BQ + b) * DQ + d];
    long base = ((long)(b * SQ + c * CH)) * DQ + d;
#pragma unroll 4
    for (int i = 0; i < CH; ++i) {
        r = fmaf(dec, r, K_[base] * V_[base]);
        g_retained[base] = Q_[base] * r;
        base += DQ;
    }
}

// ---------------- big fp32 GEMM: C = X @ W^T + bias (opt sigmoid) -----------
// X:[M,K] row-major, W:[N,K] row-major. 128x128 tile, BK=16, 256 thr, 8x8/thr.
__global__ __launch_bounds__(256) void gemm_nt(const float* __restrict__ X,
                                               const float* __restrict__ W,
                                               const float* __restrict__ bias,
                                               float* __restrict__ C,
                                               int M, int N, int K, int act) {
    __shared__ float Xs[16][132];
    __shared__ float Ws[16][132];
    const int tid = threadIdx.x;
    const int row0 = blockIdx.y * 128;
    const int col0 = blockIdx.x * 128;
    const int tx = tid & 15, ty = tid >> 4;
    const int lr = tid >> 2, lc = (tid & 3) << 2;
    const float* Xp = X + (long)(row0 + lr) * K + lc;
    const float* Wp = W + (long)(col0 + lr) * K + lc;
    float acc[8][8] = {};
    for (int k0 = 0; k0 < K; k0 += 16) {
        float4 xa = *(const float4*)(Xp + k0);
        float4 xb = *(const float4*)(Xp + 64L * K + k0);
        float4 wa = *(const float4*)(Wp + k0);
        float4 wb = *(const float4*)(Wp + 64L * K + k0);
        __syncthreads();
        Xs[lc + 0][lr] = xa.x; Xs[lc + 1][lr] = xa.y; Xs[lc + 2][lr] = xa.z; Xs[lc + 3][lr] = xa.w;
        Xs[lc + 0][lr + 64] = xb.x; Xs[lc + 1][lr + 64] = xb.y; Xs[lc + 2][lr + 64] = xb.z; Xs[lc + 3][lr + 64] = xb.w;
        Ws[lc + 0][lr] = wa.x; Ws[lc + 1][lr] = wa.y; Ws[lc + 2][lr] = wa.z; Ws[lc + 3][lr] = wa.w;
        Ws[lc + 0][lr + 64] = wb.x; Ws[lc + 1][lr + 64] = wb.y; Ws[lc + 2][lr + 64] = wb.z; Ws[lc + 3][lr + 64] = wb.w;
        __syncthreads();
#pragma unroll
        for (int kk = 0; kk < 16; ++kk) {
            float a[8], br[8];
            *(float4*)(a)     = *(const float4*)&Xs[kk][ty * 8];
            *(float4*)(a + 4) = *(const float4*)&Xs[kk][ty * 8 + 4];
            *(float4*)(br)     = *(const float4*)&Ws[kk][tx * 8];
            *(float4*)(br + 4) = *(const float4*)&Ws[kk][tx * 8 + 4];
#pragma unroll
            for (int i = 0; i < 8; ++i)
#pragma unroll
                for (int jj = 0; jj < 8; ++jj)
                    acc[i][jj] = fmaf(a[i], br[jj], acc[i][jj]);
        }
    }
    float bj[8];
#pragma unroll
    for (int jj = 0; jj < 8; ++jj) bj[jj] = bias ? bias[col0 + tx * 8 + jj] : 0.f;
#pragma unroll
    for (int i = 0; i < 8; ++i) {
        long row = row0 + ty * 8 + i;
        float o[8];
#pragma unroll
        for (int jj = 0; jj < 8; ++jj) {
            float v = acc[i][jj] + bj[jj];
            if (act) v = 1.f / (1.f + expf(-v));
            o[jj] = v;
        }
        *(float4*)&C[row * N + col0 + tx * 8]     = make_float4(o[0], o[1], o[2], o[3]);
        *(float4*)&C[row * N + col0 + tx * 8 + 4] = make_float4(o[4], o[5], o[6], o[7]);
    }
}

// ---------------- persistent sequential scan (the A GEMM recurrence) --------
// 128 CTAs, each owns 8 columns of A (SMEM-resident). One grid barrier/step.
#define SCAN_SMEM ((8*1028 + 4*1028 + 256) * 4)

__global__ __launch_bounds__(TPB, 1) void scan_kernel(const float* __restrict__ A) {
    extern __shared__ float sm[];
    float* As = sm;                        // 8 rows x 1028 (padded, conflict-free)
    float* bl = sm + 8 * 1028;             // 4 rows x 1028
    float* part = sm + 8 * 1028 + 4 * 1028; // 8 warps x 32
    const int tid = threadIdx.x, w = tid >> 5, lane = tid & 31;
    const int c0 = blockIdx.x * 8;

    // load A slice (once for the whole scan)
    for (int i = tid; i < 8 * DQ; i += TPB) {
        int j = i >> 10, kk = i & 1023;
        As[j * 1028 + kk] = A[(long)(c0 + j) * DQ + kk];
    }

    const int j = lane >> 2, b = lane & 3; // warp0 lane -> (col, batch)
    const int colg = c0 + j;
    float st = 0.f, gv = 0.f, iv = 0.f, mv = 0.f, mv_nx = 0.f;
    if (w == 0) {
        long off = (long)(b * SQ) * DQ + colg;
        gv = g_gate[off]; iv = g_inp[off]; mv = g_bm[off];
    }
    __syncthreads();

    unsigned ep = 0;
    for (int t = 0; t < SQ; ++t) {
        const int p = t & 1;
        if (w == 0) {
            float blv = gv * st + (1.f - gv) * iv;   // blended slice (local)
            g_blend[p][b * DQ + colg] = blv;
            __threadfence();
        }
        __syncthreads();
        // ---- grid barrier ----
        if (tid == 0) {
            unsigned a = atomicAdd(&g_arrive, 1u);
            if (a == NCTA - 1) {
                g_arrive = 0u;
                __threadfence();
                atomicAdd(&g_epoch, 1u);
            } else {
                unsigned e;
                do {
                    asm volatile("ld.acquire.gpu.u32 %0, [%1];" : "=r"(e) : "l"(&g_epoch));
                } while (e <= ep);
            }
        }
        __syncthreads();
        ++ep;
        // prefetch next step's gate/inp/inpBm (overlaps with GEMM below)
        if (w == 0 && t + 1 < SQ) {
            long off = ((long)b * SQ + (t + 1)) * DQ + colg;
            gv = g_gate[off]; iv = g_inp[off]; mv_nx = g_bm[off];
        }
        // gather full blended vector into SMEM
        const float* gb = g_blend[p];
        for (int i4 = tid; i4 < BQ * DQ / 4; i4 += TPB) {
            float4 x = ((const float4*)gb)[i4];
            int bb = i4 >> 8, kk = (i4 & 255) << 2;
            *(float4*)(bl + bb * 1028 + kk) = x;
        }
        __syncthreads();
        // K-split GEMM: warp w covers k in [128w, 128w+128), lane owns (j,b)
        float a0 = 0.f, a1 = 0.f, a2 = 0.f, a3 = 0.f;
        const float* Aj = As + j * 1028 + w * 128;
        const float* Bb = bl + b * 1028 + w * 128;
#pragma unroll
        for (int kk = 0; kk < 128; kk += 4) {
            float4 av = *(const float4*)(Aj + kk);
            float4 bv = *(const float4*)(Bb + kk);
            a0 = fmaf(av.x, bv.x, a0);
            a1 = fmaf(av.y, bv.y, a1);
            a2 = fmaf(av.z, bv.z, a2);
            a3 = fmaf(av.w, bv.w, a3);
        }
        part[w * 32 + lane] = (a0 + a1) + (a2 + a3);
        __syncthreads();
        if (w == 0) {
            float ssum = 0.f;
#pragma unroll
            for (int q8 = 0; q8 < 8; ++q8) ssum += part[q8 * 32 + lane];
            st = tanhf(ssum + mv);
            g_states[((long)b * SQ + t) * DQ + colg] = st;
            mv = mv_nx;
        }
    }
}

// ---------------- launch ----------------------------------------------------
extern "C" void kernel_launch(void* const* d_in, const int* in_sizes, int n_in,
                              void* d_out, int out_size) {
    const float* q     = (const float*)d_in[0];
    const float* k     = (const float*)d_in[1];
    const float* v     = (const float*)d_in[2];
    const float* Wi    = (const float*)d_in[3];
    const float* bi    = (const float*)d_in[4];
    const float* Wg    = (const float*)d_in[5];
    const float* bg    = (const float*)d_in[6];
    const float* A     = (const float*)d_in[7];
    const float* Bm    = (const float*)d_in[8];
    const float* Wo    = (const float*)d_in[9];
    const float* bo    = (const float*)d_in[10];
    const float* decay = (const float*)d_in[11];
    float* out = (float*)d_out;

    float *retained, *inp, *gate, *bm, *states;
    cudaGetSymbolAddress((void**)&retained, g_retained);
    cudaGetSymbolAddress((void**)&inp, g_inp);
    cudaGetSymbolAddress((void**)&gate, g_gate);
    cudaGetSymbolAddress((void**)&bm, g_bm);
    cudaGetSymbolAddress((void**)&states, g_states);

    cudaFuncSetAttribute(scan_kernel, cudaFuncAttributeMaxDynamicSharedMemorySize, SCAN_SMEM);

    // 1) retention prefix scan -> retained
    ret_pass1<<<(NCH * BQ * DQ) / TPB, TPB>>>(k, v, decay);
    ret_pass2<<<(BQ * DQ) / TPB, TPB>>>(decay);
    ret_pass3<<<(NCH * BQ * DQ) / TPB, TPB>>>(q, k, v, decay);

    // 2) parallel big GEMMs
    dim3 gg(DQ / 128, MROWS / 128);
    gemm_nt<<<gg, 256>>>(retained, Wi, bi, inp, MROWS, DQ, DQ, 0);
    gemm_nt<<<gg, 256>>>(inp, Wg, bg, gate, MROWS, DQ, DQ, 1);
    gemm_nt<<<gg, 256>>>(inp, Bm, (const float*)nullptr, bm, MROWS, DQ, DQ, 0);

    // 3) sequential state recurrence (persistent, one grid barrier per step)
    reset_bar<<<1, 1>>>();
    scan_kernel<<<NCTA, TPB, SCAN_SMEM>>>(A);

    // 4) output projection
    gemm_nt<<<gg, 256>>>(states, Wo, bo, out, MROWS, DQ, DQ, 0);
}